// round 1
// baseline (speedup 1.0000x reference)
#include <cuda_runtime.h>
#include <cuda_bf16.h>
#include <math.h>

// Problem constants
#define BB 8
#define SS 4096
#define DD 1024
#define AA 3
#define CC 2
#define KK 64
#define AC 6
#define SA (SS*AA)            // 12288 per batch
#define NROWS (BB*SS)         // 32768
#define MARGIN 5.0f

// Scratch (no allocations allowed)
__device__ float g_logits[NROWS * AC];                 // 786 KB
__device__ unsigned long long g_keys[BB * SA];         // 786 KB
__device__ unsigned long long g_sel[BB * KK];          // 4 KB
__device__ int g_is64;

// ---------------------------------------------------------------------------
// Kernel 0: detect whether anchor_labels buffer is int64 or int32.
// Values are 0/1. If int64 little-endian, every odd 32-bit word is 0.
// If int32, odd words are ~50% ones. Check 512 odd words (P(false int64)=2^-512).
// ---------------------------------------------------------------------------
__global__ void detect_kernel(const int* __restrict__ labels_raw) {
    int lane = threadIdx.x;
    int nz = 0;
    for (int m = lane; m < 512; m += 32)
        nz |= (labels_raw[2*m + 1] != 0);
    unsigned mask = __ballot_sync(0xFFFFFFFFu, nz);
    if (lane == 0) g_is64 = (mask == 0u) ? 1 : 0;
}

__device__ __forceinline__ int read_label(const int* __restrict__ p, int idx, int is64) {
    return is64 ? p[2*idx] : p[idx];   // low word suffices for values 0/1
}

// ---------------------------------------------------------------------------
// Kernel 1: fused GEMV + predict_label + topk-key generation.
// 256 threads / block, 8 warps, 4 rows per warp -> 32 rows/block, 1024 blocks.
// W transposed to shared Wt[j][d] so warp-wide LDS.128 is conflict-free; each
// W load amortizes over 4 rows to keep smem traffic below the DRAM floor.
// ---------------------------------------------------------------------------
__global__ void __launch_bounds__(256)
main_kernel(const float* __restrict__ X, const float* __restrict__ W,
            const float* __restrict__ bias, const int* __restrict__ labels,
            float* __restrict__ out_predict) {
    __shared__ float sW[AC * DD];   // Wt[j][d], 24 KB
    __shared__ float sb[AC];

    for (int o = threadIdx.x; o < AC * DD; o += 256) {
        int j = o >> 10;            // DD = 1024
        int d = o & (DD - 1);
        sW[o] = W[d * AC + j];
    }
    if (threadIdx.x < AC) sb[threadIdx.x] = bias[threadIdx.x];
    __syncthreads();

    const int is64 = g_is64;
    const int wid  = threadIdx.x >> 5;
    const int lane = threadIdx.x & 31;
    const int gw   = blockIdx.x * 8 + wid;
    const int row0 = gw * 4;

    const float4* __restrict__ X4 = (const float4*)X;
    const float4* __restrict__ W4 = (const float4*)sW;

    float acc[4][AC];
    #pragma unroll
    for (int r = 0; r < 4; r++)
        #pragma unroll
        for (int j = 0; j < AC; j++) acc[r][j] = 0.0f;

    #pragma unroll
    for (int i = 0; i < 8; i++) {
        const int ci = lane + 32 * i;               // float4 column index
        float4 x0 = X4[(row0 + 0) * 256 + ci];
        float4 x1 = X4[(row0 + 1) * 256 + ci];
        float4 x2 = X4[(row0 + 2) * 256 + ci];
        float4 x3 = X4[(row0 + 3) * 256 + ci];
        #pragma unroll
        for (int j = 0; j < AC; j++) {
            float4 w = W4[j * 256 + ci];
            acc[0][j] += x0.x*w.x + x0.y*w.y + x0.z*w.z + x0.w*w.w;
            acc[1][j] += x1.x*w.x + x1.y*w.y + x1.z*w.z + x1.w*w.w;
            acc[2][j] += x2.x*w.x + x2.y*w.y + x2.z*w.z + x2.w*w.w;
            acc[3][j] += x3.x*w.x + x3.y*w.y + x3.z*w.z + x3.w*w.w;
        }
    }

    // Butterfly reduce: every lane ends with full sums.
    #pragma unroll
    for (int r = 0; r < 4; r++)
        #pragma unroll
        for (int j = 0; j < AC; j++)
            #pragma unroll
            for (int off = 16; off > 0; off >>= 1)
                acc[r][j] += __shfl_xor_sync(0xFFFFFFFFu, acc[r][j], off);

    if (lane < 4) {
        const int row = row0 + lane;
        float v[AC];
        #pragma unroll
        for (int j = 0; j < AC; j++) v[j] = acc[lane][j] + sb[j];

        #pragma unroll
        for (int j = 0; j < AC; j++) g_logits[row * AC + j] = v[j];

        #pragma unroll
        for (int a = 0; a < AA; a++) {
            const float x0 = v[2*a], x1 = v[2*a + 1];
            out_predict[row * AA + a] = (x1 > x0) ? 1.0f : 0.0f;  // argmax, tie->0

            const int la  = read_label(labels, row * AA + a, is64);
            const float lm = (la == 1) ? 2.0f : 1.0f / (1.0f + expf(-x1));
            // key: value desc, then smallest flat index first (matches lax.top_k)
            const unsigned vb   = __float_as_uint(lm);          // lm > 0 always
            const unsigned flat = (unsigned)((row & (SS - 1)) * AA + a);
            g_keys[row * AA + a] =
                ((unsigned long long)vb << 32) | (unsigned long long)(0xFFFFFFFFu - flat);
        }
    }
}

// ---------------------------------------------------------------------------
// Kernel 2: top-64 per batch. One block per batch.
// Phase 1: 256 threads each reduce a strided 48-element chunk to a best.
// Phase 2: warp 0 runs 64 extract-max iterations; the unique winner lane
// rescans only its invalidated 48-chunk (keys are unique -> strict order).
// ---------------------------------------------------------------------------
__global__ void __launch_bounds__(256) topk_kernel() {
    __shared__ unsigned long long bests[256];
    const int b = blockIdx.x;
    const int t = threadIdx.x;
    const unsigned long long* __restrict__ keys = g_keys + b * SA;

    unsigned long long best = 0ULL;
    #pragma unroll 4
    for (int i = 0; i < 48; i++) {
        unsigned long long k = keys[t + 256 * i];
        if (k > best) best = k;
    }
    bests[t] = best;
    __syncthreads();

    if (t < 32) {
        unsigned long long loc[8];
        unsigned long long lb = 0ULL;
        #pragma unroll
        for (int r = 0; r < 8; r++) {
            loc[r] = bests[t * 8 + r];
            if (loc[r] > lb) lb = loc[r];
        }
        for (int k = 0; k < KK; k++) {
            unsigned long long m = lb;
            #pragma unroll
            for (int off = 16; off > 0; off >>= 1) {
                unsigned long long o = __shfl_xor_sync(0xFFFFFFFFu, m, off);
                if (o > m) m = o;
            }
            if (lb == m) {  // unique winner (keys are unique & nonzero)
                g_sel[b * KK + k] = m;
                int rw = 0;
                #pragma unroll
                for (int r = 0; r < 8; r++) if (loc[r] == m) rw = r;
                const int ct = t * 8 + rw;
                unsigned long long nb = 0ULL;
                for (int i = 0; i < 48; i++) {
                    unsigned long long kk = keys[ct + 256 * i];
                    if (kk < m && kk > nb) nb = kk;
                }
                loc[rw] = nb;
                lb = 0ULL;
                #pragma unroll
                for (int r = 0; r < 8; r++) if (loc[r] > lb) lb = loc[r];
            }
        }
    }
}

// ---------------------------------------------------------------------------
// Kernel 3: decode selections, write total_idx & candidate_label, reduce loss.
// Output layout (float32): [loss(1) | predict(98304) | total_idx(1536) | cand(512)]
// ---------------------------------------------------------------------------
__global__ void __launch_bounds__(512)
finalize_kernel(const int* __restrict__ labels, float* __restrict__ out) {
    __shared__ float red[512];
    const int t = threadIdx.x;
    const int b = t >> 6;

    const unsigned long long key = g_sel[t];
    const unsigned flat = 0xFFFFFFFFu - (unsigned)(key & 0xFFFFFFFFu);
    const int s = (int)(flat / AA);
    const int a = (int)(flat - (unsigned)s * AA);
    const int row = b * SS + s;

    const int is64 = g_is64;
    const int y = read_label(labels, row * AA + a, is64);

    const float x0 = g_logits[row * AC + 2*a];
    const float x1 = g_logits[row * AC + 2*a + 1];
    const float xy = y ? x1 : x0;
    const float xo = y ? x0 : x1;
    red[t] = fmaxf(0.0f, MARGIN - xy + xo) * (1.0f / CC);

    float* ti = out + 1 + NROWS * AA;
    ti[t * 3 + 0] = (float)b;
    ti[t * 3 + 1] = (float)s;
    ti[t * 3 + 2] = (float)a;
    out[1 + NROWS * AA + BB * KK * 3 + t] = (x1 > x0) ? 1.0f : 0.0f;

    __syncthreads();
    for (int off = 256; off > 0; off >>= 1) {
        if (t < off) red[t] += red[t + off];
        __syncthreads();
    }
    if (t == 0) out[0] = red[0] / (float)(BB * KK);
}

// ---------------------------------------------------------------------------
extern "C" void kernel_launch(void* const* d_in, const int* in_sizes, int n_in,
                              void* d_out, int out_size) {
    const float* X     = (const float*)d_in[0];   // batch_input (8,4096,1024) f32
    const float* W     = (const float*)d_in[1];   // W (1024,6) f32
    const float* bias  = (const float*)d_in[2];   // b (6,) f32
    const int*   lab   = (const int*)d_in[3];     // anchor_labels (8,4096,3) i32/i64
    float* out = (float*)d_out;

    detect_kernel<<<1, 32>>>(lab);
    main_kernel<<<NROWS / 32, 256>>>(X, W, bias, lab, out + 1);
    topk_kernel<<<BB, 256>>>();
    finalize_kernel<<<1, 512>>>(lab, out);
}

// round 3
// speedup vs baseline: 1.8723x; 1.8723x over previous
#include <cuda_runtime.h>
#include <math.h>

typedef unsigned long long u64;

#define BB 8
#define SS 4096
#define DD 1024
#define AA 3
#define CC 2
#define KK 64
#define AC 6
#define SA (SS*AA)            // 12288 per batch
#define NROWS (BB*SS)         // 32768
#define MARGIN 5.0f

// Scratch (device globals; no allocations allowed)
__device__ float g_logits[NROWS * AC];     // 786 KB
__device__ int   g_selidx[BB * KK];        // flat index (0..12287) per sample
__device__ int   g_fb[BB];                 // per-batch fallback flag
__device__ int   g_is64;

// ---------------------------------------------------------------------------
__device__ __forceinline__ int read_label(const int* __restrict__ p, int idx, int is64) {
    return is64 ? p[2*idx] : p[idx];   // values are 0/1; low word suffices
}

// ---------------------------------------------------------------------------
// Kernel 1: label-dtype detection + per-batch selection of the first 64
// positive (label==1) flat positions. This equals top_k(lm[:,1], 64) whenever
// the batch has >=64 positives, because positives score exactly 2.0 (> any
// sigmoid < 1) and lax.top_k breaks ties by smallest index. If a batch has
// <64 positives, flag g_fb[b] and the finalize kernel runs a general
// selection. One block per batch, 256 threads, contiguous 48-elem chunks.
// ---------------------------------------------------------------------------
__global__ void __launch_bounds__(256) select_kernel(const int* __restrict__ lab) {
    __shared__ int s_wtot[8];
    __shared__ unsigned s_or[8];
    __shared__ int s_is64;
    const int t = threadIdx.x, b = blockIdx.x;
    const int lane = t & 31, wid = t >> 5;

    // dtype detection: if int64 little-endian, odd 32-bit words are all zero.
    int nz = (lab[2*t + 1] != 0) | (lab[2*t + 513] != 0);
    unsigned bal = __ballot_sync(0xFFFFFFFFu, nz);
    if (lane == 0) s_or[wid] = bal;
    __syncthreads();
    if (t == 0) {
        unsigned o = 0;
        #pragma unroll
        for (int w = 0; w < 8; w++) o |= s_or[w];
        int is64 = (o == 0u) ? 1 : 0;
        s_is64 = is64;
        if (b == 0) g_is64 = is64;
    }
    __syncthreads();
    const int is64 = s_is64;

    const int base = b * SA + t * 48;
    int cnt = 0;
    #pragma unroll 8
    for (int i = 0; i < 48; i++) cnt += (read_label(lab, base + i, is64) == 1);

    // block inclusive scan of per-thread counts
    int incl = cnt;
    #pragma unroll
    for (int off = 1; off < 32; off <<= 1) {
        int n = __shfl_up_sync(0xFFFFFFFFu, incl, off);
        if (lane >= off) incl += n;
    }
    if (lane == 31) s_wtot[wid] = incl;
    __syncthreads();
    int woff = 0;
    for (int w = 0; w < wid; w++) woff += s_wtot[w];
    const int excl = woff + incl - cnt;

    if (t == 0) {
        int tot = 0;
        #pragma unroll
        for (int w = 0; w < 8; w++) tot += s_wtot[w];
        g_fb[b] = (tot < KK) ? 1 : 0;   // rewritten every replay (deterministic)
    }

    // only the first few threads ever take this branch
    if (excl < KK && cnt > 0) {
        int rank = excl;
        for (int i = 0; i < 48; i++) {
            if (read_label(lab, base + i, is64) == 1) {
                if (rank < KK) g_selidx[b * KK + rank] = t * 48 + i;
                rank++;
            }
        }
    }
}

// ---------------------------------------------------------------------------
// Kernel 2: GEMV (B*S,1024)@(1024,6) + predict_label + logits store.
// 256 threads, 8 warps, 4 rows/warp. W transposed into shared (conflict-free
// LDS.128 amortized over 4 rows). Scalar FFMA inner product (known-good on
// sm_100a); DRAM-bound by design.
// ---------------------------------------------------------------------------
__global__ void __launch_bounds__(256)
main_kernel(const float* __restrict__ X, const float* __restrict__ W,
            const float* __restrict__ bias, float* __restrict__ out_predict) {
    __shared__ float sW[AC * DD];   // Wt[j][d], 24 KB
    __shared__ float sb[AC];

    for (int o = threadIdx.x; o < AC * DD; o += 256) {
        int j = o >> 10;
        int d = o & (DD - 1);
        sW[o] = W[d * AC + j];
    }
    if (threadIdx.x < AC) sb[threadIdx.x] = bias[threadIdx.x];
    __syncthreads();

    const int wid  = threadIdx.x >> 5;
    const int lane = threadIdx.x & 31;
    const int row0 = (blockIdx.x * 8 + wid) * 4;

    const float4* __restrict__ X4 = (const float4*)X;
    const float4* __restrict__ W4 = (const float4*)sW;

    float acc[4][AC];
    #pragma unroll
    for (int r = 0; r < 4; r++)
        #pragma unroll
        for (int j = 0; j < AC; j++) acc[r][j] = 0.0f;

    #pragma unroll
    for (int i = 0; i < 8; i++) {
        const int ci = lane + 32 * i;               // float4 column index
        float4 x0 = X4[(row0 + 0) * 256 + ci];
        float4 x1 = X4[(row0 + 1) * 256 + ci];
        float4 x2 = X4[(row0 + 2) * 256 + ci];
        float4 x3 = X4[(row0 + 3) * 256 + ci];
        #pragma unroll
        for (int j = 0; j < AC; j++) {
            float4 w = W4[j * 256 + ci];
            acc[0][j] += x0.x*w.x + x0.y*w.y + x0.z*w.z + x0.w*w.w;
            acc[1][j] += x1.x*w.x + x1.y*w.y + x1.z*w.z + x1.w*w.w;
            acc[2][j] += x2.x*w.x + x2.y*w.y + x2.z*w.z + x2.w*w.w;
            acc[3][j] += x3.x*w.x + x3.y*w.y + x3.z*w.z + x3.w*w.w;
        }
    }

    // Butterfly reduce: every lane ends with full sums.
    #pragma unroll
    for (int r = 0; r < 4; r++)
        #pragma unroll
        for (int j = 0; j < AC; j++)
            #pragma unroll
            for (int off = 16; off > 0; off >>= 1)
                acc[r][j] += __shfl_xor_sync(0xFFFFFFFFu, acc[r][j], off);

    if (lane < 4) {
        const int row = row0 + lane;
        float v[AC];
        #pragma unroll
        for (int j = 0; j < AC; j++) {
            v[j] = acc[lane][j] + sb[j];
            g_logits[row * AC + j] = v[j];
        }
        #pragma unroll
        for (int a = 0; a < AA; a++)
            out_predict[row * AA + a] = (v[2*a + 1] > v[2*a]) ? 1.0f : 0.0f;
    }
}

// ---------------------------------------------------------------------------
// Kernel 3: fallback selection (only if some batch had <64 positives — never
// on the benchmark inputs), then decode samples, write total_idx &
// candidate_label, reduce margin loss via shuffles.
// Output layout (f32): [loss(1) | predict(98304) | total_idx(1536) | cand(512)]
// ---------------------------------------------------------------------------
__device__ __forceinline__ u64 make_key(const int* __restrict__ lab, int b, int f, int is64) {
    const int row = b * SS + f / AA;
    const int a = f - (f / AA) * AA;
    const int la = read_label(lab, row * AA + a, is64);
    const float x1 = g_logits[row * AC + 2*a + 1];
    const float lm = (la == 1) ? 2.0f : 1.0f / (1.0f + expf(-x1));
    return ((u64)__float_as_uint(lm) << 32) | (u64)(0xFFFFFFFFu - (unsigned)f);
}

__global__ void __launch_bounds__(512)
finalize_kernel(const int* __restrict__ lab, float* __restrict__ out) {
    __shared__ float s_part[16];
    const int t = threadIdx.x;
    const int lane = t & 31, wid = t >> 5;
    const int is64 = g_is64;

    // General warp-level top-64 fallback: warp w handles batch w when flagged.
    if (wid < BB && g_fb[wid]) {
        const int b = wid;
        u64 lb = 0ULL;
        for (int i = 0; i < SA / 32; i++) {
            u64 k = make_key(lab, b, lane * (SA / 32) + i, is64);
            if (k > lb) lb = k;
        }
        for (int k = 0; k < KK; k++) {
            u64 m = lb;
            #pragma unroll
            for (int off = 16; off > 0; off >>= 1) {
                u64 o = __shfl_xor_sync(0xFFFFFFFFu, m, off);
                if (o > m) m = o;
            }
            if (lb == m) {   // unique keys -> unique winner
                g_selidx[b * KK + k] = (int)(0xFFFFFFFFu - (unsigned)(m & 0xFFFFFFFFu));
                u64 nb = 0ULL;
                for (int i = 0; i < SA / 32; i++) {
                    u64 kk = make_key(lab, b, lane * (SA / 32) + i, is64);
                    if (kk < m && kk > nb) nb = kk;
                }
                lb = nb;
            }
        }
    }
    __syncthreads();

    const int b = t >> 6;
    const int flat = g_selidx[t];
    const int s = flat / AA;
    const int a = flat - s * AA;
    const int row = b * SS + s;

    const int y = read_label(lab, row * AA + a, is64);
    const float x0 = g_logits[row * AC + 2*a];
    const float x1 = g_logits[row * AC + 2*a + 1];
    const float xy = y ? x1 : x0;
    const float xo = y ? x0 : x1;
    float l = fmaxf(0.0f, MARGIN - xy + xo) * (1.0f / CC);

    float* ti = out + 1 + NROWS * AA;
    ti[t * 3 + 0] = (float)b;
    ti[t * 3 + 1] = (float)s;
    ti[t * 3 + 2] = (float)a;
    out[1 + NROWS * AA + BB * KK * 3 + t] = (x1 > x0) ? 1.0f : 0.0f;

    #pragma unroll
    for (int off = 16; off > 0; off >>= 1)
        l += __shfl_xor_sync(0xFFFFFFFFu, l, off);
    if (lane == 0) s_part[wid] = l;
    __syncthreads();
    if (t == 0) {
        float sum = 0.0f;
        #pragma unroll
        for (int w = 0; w < 16; w++) sum += s_part[w];
        out[0] = sum / (float)(BB * KK);
    }
}

// ---------------------------------------------------------------------------
extern "C" void kernel_launch(void* const* d_in, const int* in_sizes, int n_in,
                              void* d_out, int out_size) {
    const float* X    = (const float*)d_in[0];   // (8,4096,1024) f32
    const float* W    = (const float*)d_in[1];   // (1024,6) f32
    const float* bias = (const float*)d_in[2];   // (6,) f32
    const int*   lab  = (const int*)d_in[3];     // (8,4096,3) i32/i64
    float* out = (float*)d_out;

    select_kernel<<<BB, 256>>>(lab);
    main_kernel<<<NROWS / 32, 256>>>(X, W, bias, out + 1);
    finalize_kernel<<<1, 512>>>(lab, out);
}